// round 2
// baseline (speedup 1.0000x reference)
#include <cuda_runtime.h>

#define NN 100000
#define HH 64
#define EMAX 1600000
#define BN_EPS 1e-5f

// ---- scratch (static device globals; float4-typed for 16B alignment) ----
__device__ float4 g_bufA[NN * HH / 4];   // hs1 -> h1
__device__ float4 g_bufB[NN * HH / 4];   // accumulator
__device__ float4 g_bufC[NN * HH / 4];   // hs2 -> h2
__device__ int   g_src[EMAX];
__device__ int   g_dst[EMAX];
__device__ int   g_is64;
__device__ float g_deg[NN];
__device__ float g_dinv[NN];
__device__ float g_stats1[128];          // sum[64], sumsq[64]
__device__ float g_stats2[128];
__device__ float g_bn1[128];             // a[64], c[64]
__device__ float g_bn2[128];

// ---- detect int64 vs int32 edge_index (JAX x64-off demotes to int32) ----
__global__ void k_detect(const unsigned int* __restrict__ ei) {
    __shared__ unsigned int s;
    if (threadIdx.x == 0) s = 0u;
    __syncthreads();
    atomicOr(&s, ei[threadIdx.x * 2 + 1]);   // high words if int64
    __syncthreads();
    if (threadIdx.x == 0) g_is64 = (s == 0u) ? 1 : 0;
}

// ---- convert indices to int32 scratch ----
__global__ void k_cvt(const void* __restrict__ ei, int E) {
    int e = blockIdx.x * 256 + threadIdx.x;
    if (e >= E) return;
    if (g_is64) {
        const long long* p = (const long long*)ei;
        g_src[e] = (int)p[e];
        g_dst[e] = (int)p[e + E];
    } else {
        const int* p = (const int*)ei;
        g_src[e] = p[e];
        g_dst[e] = p[e + E];
    }
}

// ---- zero accumulators / stats / deg ----
__global__ void k_zero() {
    int i = blockIdx.x * 256 + threadIdx.x;
    if (i < NN * HH / 4) g_bufB[i] = make_float4(0.f, 0.f, 0.f, 0.f);
    if (i < NN) g_deg[i] = 0.0f;
    if (i < 128) { g_stats1[i] = 0.0f; g_stats2[i] = 0.0f; }
}

// ---- degree (in-degree of dst) ----
__global__ void k_deg(int E) {
    int e = blockIdx.x * 256 + threadIdx.x;
    if (e < E) atomicAdd(&g_deg[g_dst[e]], 1.0f);
}

__global__ void k_dinv() {
    int v = blockIdx.x * 256 + threadIdx.x;
    if (v < NN) g_dinv[v] = rsqrtf(g_deg[v] + 1.0f);   // +1 self-loop
}

// ---- GEMM: out[r] = ((a*X[r]+c) @ W) * rowscale[r] + (bias + c@W)
// X: [N,64], W: [64,NOUT]. bn = {a[64], c[64]} or null. One thread per row,
// 128 rows/block, packed f32x2 FMA inner loop, smem-staged coalesced IO.
template <int NOUT>
__global__ void __launch_bounds__(128) k_gemm(
    const float* __restrict__ X, const float* __restrict__ Wg,
    const float* __restrict__ bn, const float* __restrict__ rowscale,
    const float* __restrict__ bias, float* __restrict__ out)
{
    extern __shared__ float sm[];
    float* Xs   = sm;                 // 128 * 65 (pad 65 -> conflict-free)
    float* Ws   = sm + 128 * 65;      // 64 * NOUT (pre-scaled by a[k])
    float* Init = Ws + 64 * NOUT;     // NOUT

    const int t = threadIdx.x;
    const long row0 = (long)blockIdx.x * 128;

    // load X tile (coalesced float4, scalar smem stores for pad-65 layout)
    #pragma unroll
    for (int i = 0; i < 16; i++) {
        int lin = t + i * 128;
        int r = lin >> 4, q = lin & 15;
        long gr = row0 + r;
        float4 v = (gr < NN) ? reinterpret_cast<const float4*>(X)[gr * 16 + q]
                             : make_float4(0.f, 0.f, 0.f, 0.f);
        float* p = &Xs[r * 65 + q * 4];
        p[0] = v.x; p[1] = v.y; p[2] = v.z; p[3] = v.w;
    }
    // load W, folding per-K affine scale a[k]
    #pragma unroll
    for (int i = t; i < 16 * NOUT; i += 128) {
        int k = (i * 4) / NOUT;
        float a = bn ? bn[k] : 1.0f;
        float4 w = reinterpret_cast<const float4*>(Wg)[i];
        reinterpret_cast<float4*>(Ws)[i] = make_float4(w.x * a, w.y * a, w.z * a, w.w * a);
    }
    // constant row: bias[j] + sum_k c[k]*W[k][j]
    if (t < NOUT) {
        float s = bias ? bias[t] : 0.0f;
        if (bn) {
            #pragma unroll 8
            for (int k = 0; k < 64; k++) s += bn[64 + k] * Wg[k * NOUT + t];
        }
        Init[t] = s;
    }
    __syncthreads();

    unsigned long long acc[NOUT / 2];
    #pragma unroll
    for (int j = 0; j < NOUT / 2; j++) {
        float2 iv = reinterpret_cast<const float2*>(Init)[j];
        asm("mov.b64 %0, {%1, %2};" : "=l"(acc[j]) : "f"(iv.x), "f"(iv.y));
    }
    const float* xr = &Xs[t * 65];
    #pragma unroll 4
    for (int k = 0; k < 64; k++) {
        float xv = xr[k];
        unsigned long long xx;
        asm("mov.b64 %0, {%1, %1};" : "=l"(xx) : "f"(xv));
        const unsigned long long* wr =
            reinterpret_cast<const unsigned long long*>(&Ws[k * NOUT]);
        #pragma unroll
        for (int j = 0; j < NOUT / 2; j++)
            asm("fma.rn.f32x2 %0, %1, %2, %0;" : "+l"(acc[j]) : "l"(xx), "l"(wr[j]));
    }

    long r = row0 + t;
    float rs = 1.0f;
    if (rowscale && r < NN) rs = rowscale[r];

    __syncthreads();   // done reading Xs -> reuse as output staging
    #pragma unroll
    for (int j = 0; j < NOUT / 2; j++) {
        float lo, hi;
        asm("mov.b64 {%0, %1}, %2;" : "=f"(lo), "=f"(hi) : "l"(acc[j]));
        Xs[t * 65 + 2 * j]     = lo * rs;
        Xs[t * 65 + 2 * j + 1] = hi * rs;
    }
    __syncthreads();
    constexpr int Q = NOUT / 4;
    #pragma unroll
    for (int i = 0; i < Q; i++) {
        int lin = t + i * 128;
        int r2 = lin / Q, q = lin % Q;
        long gr = row0 + r2;
        if (gr < NN) {
            float* p = &Xs[r2 * 65 + q * 4];
            reinterpret_cast<float4*>(out)[gr * Q + q] = make_float4(p[0], p[1], p[2], p[3]);
        }
    }
}

// ---- edge scatter: acc[dst] += hs[src]  (16 threads/edge, float4 REDG) ----
__global__ void k_scat(const float4* __restrict__ hs, float4* __restrict__ acc, int E)
{
    long idx = (long)blockIdx.x * 256 + threadIdx.x;
    if (idx >= (long)E * 16) return;
    int e = (int)(idx >> 4);
    int q = (int)(idx & 15);
    int s = g_src[e], d = g_dst[e];
    float4 v = hs[(long)s * 16 + q];
    float4* p = acc + (long)d * 16 + q;
    asm volatile("red.global.add.v4.f32 [%0], {%1,%2,%3,%4};"
                 :: "l"(p), "f"(v.x), "f"(v.y), "f"(v.z), "f"(v.w) : "memory");
}

// ---- epilogue: h = relu(dinv*(acc+hs)+b); BN stats; optionally re-zero acc ----
template <bool ZERO_ACC>
__global__ void k_epi(const float4* hs, float4* acc, const float* __restrict__ bias,
                      float4* out, float* __restrict__ stats)
{
    __shared__ float ssum[64], ssq[64];
    int t = threadIdx.x;
    if (t < 64) { ssum[t] = 0.0f; ssq[t] = 0.0f; }
    __syncthreads();
    long idx = (long)blockIdx.x * 256 + t;
    if (idx < (long)NN * 16) {
        int v = (int)(idx >> 4);
        int q = (int)(idx & 15);
        float4 a = acc[idx];
        float4 h = hs[idx];
        float di = g_dinv[v];
        float4 b = reinterpret_cast<const float4*>(bias)[q];
        float4 o;
        o.x = fmaxf(fmaf(di, a.x + h.x, b.x), 0.0f);
        o.y = fmaxf(fmaf(di, a.y + h.y, b.y), 0.0f);
        o.z = fmaxf(fmaf(di, a.z + h.z, b.z), 0.0f);
        o.w = fmaxf(fmaf(di, a.w + h.w, b.w), 0.0f);
        out[idx] = o;
        if (ZERO_ACC) acc[idx] = make_float4(0.f, 0.f, 0.f, 0.f);
        int j = q * 4;
        atomicAdd(&ssum[j + 0], o.x); atomicAdd(&ssq[j + 0], o.x * o.x);
        atomicAdd(&ssum[j + 1], o.y); atomicAdd(&ssq[j + 1], o.y * o.y);
        atomicAdd(&ssum[j + 2], o.z); atomicAdd(&ssq[j + 2], o.z * o.z);
        atomicAdd(&ssum[j + 3], o.w); atomicAdd(&ssq[j + 3], o.w * o.w);
    }
    __syncthreads();
    if (t < 64) {
        atomicAdd(&stats[t], ssum[t]);
        atomicAdd(&stats[64 + t], ssq[t]);
    }
}

// ---- BN coefficients: a = gamma*rsqrt(var+eps), c = beta - mu*a ----
__global__ void k_bn(const float* __restrict__ stats, const float* __restrict__ gamma,
                     const float* __restrict__ beta, float* __restrict__ bn)
{
    int j = threadIdx.x;
    if (j < 64) {
        float mu  = stats[j] * (1.0f / NN);
        float var = stats[64 + j] * (1.0f / NN) - mu * mu;
        float a = gamma[j] * rsqrtf(var + BN_EPS);
        bn[j] = a;
        bn[64 + j] = beta[j] - mu * a;
    }
}

extern "C" void kernel_launch(void* const* d_in, const int* in_sizes, int n_in,
                              void* d_out, int out_size)
{
    const float* x      = (const float*)d_in[0];
    const void*  ei     = d_in[1];
    const float* W1     = (const float*)d_in[2];
    const float* b1     = (const float*)d_in[3];
    const float* gamma1 = (const float*)d_in[4];
    const float* beta1  = (const float*)d_in[5];
    const float* W2     = (const float*)d_in[6];
    const float* b2     = (const float*)d_in[7];
    const float* gamma2 = (const float*)d_in[8];
    const float* beta2  = (const float*)d_in[9];
    const float* Wfc    = (const float*)d_in[10];
    const float* bfc    = (const float*)d_in[11];
    float* out = (float*)d_out;

    int E = in_sizes[1] / 2;
    if (E > EMAX) E = EMAX;

    float4 *pA, *pB, *pC;
    float *ps1, *ps2, *pbn1, *pbn2;
    cudaGetSymbolAddress((void**)&pA, g_bufA);
    cudaGetSymbolAddress((void**)&pB, g_bufB);
    cudaGetSymbolAddress((void**)&pC, g_bufC);
    cudaGetSymbolAddress((void**)&ps1, g_stats1);
    cudaGetSymbolAddress((void**)&ps2, g_stats2);
    cudaGetSymbolAddress((void**)&pbn1, g_bn1);
    cudaGetSymbolAddress((void**)&pbn2, g_bn2);
    float* pdinv;
    cudaGetSymbolAddress((void**)&pdinv, g_dinv);

    const int smem64 = (128 * 65 + 64 * 64 + 64) * (int)sizeof(float);
    const int smem32 = (128 * 65 + 64 * 32 + 32) * (int)sizeof(float);
    cudaFuncSetAttribute(k_gemm<64>, cudaFuncAttributeMaxDynamicSharedMemorySize, smem64);
    cudaFuncSetAttribute(k_gemm<32>, cudaFuncAttributeMaxDynamicSharedMemorySize, smem32);

    const int GB = (NN + 127) / 128;
    long scat_items = (long)E * 16;
    int scat_blocks = (int)((scat_items + 255) / 256);

    k_detect<<<1, 256>>>((const unsigned int*)ei);
    k_cvt<<<(E + 255) / 256, 256>>>(ei, E);
    k_zero<<<6250, 256>>>();
    k_deg<<<(E + 255) / 256, 256>>>(E);
    k_dinv<<<(NN + 255) / 256, 256>>>();

    // layer 1: hs1 = (x@W1)*dinv -> scatter -> h1 = relu(dinv*(acc+hs1)+b1), stats1
    k_gemm<64><<<GB, 128, smem64>>>(x, W1, nullptr, pdinv, nullptr, (float*)pA);
    k_scat<<<scat_blocks, 256>>>(pA, pB, E);
    k_epi<true><<<6250, 256>>>(pA, pB, b1, pA, ps1);
    k_bn<<<1, 64>>>(ps1, gamma1, beta1, pbn1);

    // layer 2: hs2 = ((a1*h1+c1)@W2)*dinv -> scatter -> h2, stats2
    k_gemm<64><<<GB, 128, smem64>>>((float*)pA, W2, pbn1, pdinv, nullptr, (float*)pC);
    k_scat<<<scat_blocks, 256>>>(pC, pB, E);
    k_epi<false><<<6250, 256>>>(pC, pB, b2, pC, ps2);
    k_bn<<<1, 64>>>(ps2, gamma2, beta2, pbn2);

    // final: out = (a2*h2+c2)@Wfc + (bfc + c2@Wfc)
    k_gemm<32><<<GB, 128, smem32>>>((float*)pC, Wfc, pbn2, nullptr, bfc, out);
}